// round 3
// baseline (speedup 1.0000x reference)
#include <cuda_runtime.h>
#include <math.h>

#define NN 50000
#define EE 800000
#define HID 128
#define GG 128
#define LAT 32
#define NEG 0.2f

// ---------------- scratch (static device memory; no allocations) ----------------
__device__ float g_h[NN * HID];
__device__ float g_y[NN * HID];
__device__ float g_as[NN * 4];
__device__ float g_ad[NN * 4];
__device__ int   g_deg[NN];
__device__ int   g_rowoff[NN + 1];
__device__ int   g_cur[NN];
__device__ int   g_csr[EE + NN];
__device__ int   g_goff[GG + 1];
__device__ float g_pool[GG * HID];

#define FFMA2(d, a, b, c) \
    asm("fma.rn.f32x2 %0, %1, %2, %3;" : "=l"(d) : "l"(a), "l"(b), "l"(c))

// ---------------- CSR build ----------------
__global__ void init_kernel() {
    int i = blockIdx.x * blockDim.x + threadIdx.x;
    if (i < NN) g_deg[i] = 1;                 // self loop
}

__global__ void hist_kernel(const int* __restrict__ dst) {
    int i = blockIdx.x * blockDim.x + threadIdx.x;
    if (i < EE) atomicAdd(&g_deg[dst[i]], 1);
}

__global__ void scan_kernel() {
    __shared__ int sums[1024];
    const int T = 1024;
    int t = threadIdx.x;
    const int chunk = (NN + T - 1) / T;
    int start = t * chunk;
    int end = min(start + chunk, NN);
    int s = 0;
    for (int i = start; i < end; i++) s += g_deg[i];
    sums[t] = s;
    __syncthreads();
    for (int off = 1; off < T; off <<= 1) {
        int v = 0;
        if (t >= off) v = sums[t - off];
        __syncthreads();
        if (t >= off) sums[t] += v;
        __syncthreads();
    }
    int base = (t == 0) ? 0 : sums[t - 1];
    for (int i = start; i < end; i++) {
        g_rowoff[i] = base;
        g_cur[i] = base;
        base += g_deg[i];
    }
    if (t == 0) g_rowoff[NN] = sums[T - 1];
}

__global__ void scatter_kernel(const int* __restrict__ src, const int* __restrict__ dst) {
    int i = blockIdx.x * blockDim.x + threadIdx.x;
    if (i < EE) {
        int d = dst[i];
        int pos = atomicAdd(&g_cur[d], 1);
        g_csr[pos] = src[i];
    } else if (i < EE + NN) {
        int n = i - EE;
        int pos = atomicAdd(&g_cur[n], 1);
        g_csr[pos] = n;
    }
}

// group boundaries from sorted batch
__global__ void gbound_kernel(const int* __restrict__ batch) {
    int i = blockIdx.x * blockDim.x + threadIdx.x;
    if (i >= NN) return;
    int b = batch[i];
    int prev = (i == 0) ? -1 : batch[i - 1];
    for (int g = prev + 1; g <= b; g++) g_goff[g] = i;
    if (i == NN - 1) {
        for (int g = b + 1; g <= GG; g++) g_goff[g] = NN;
    }
}

// ---------------- GEMM + fused alpha ----------------
// Out[n,128] = X[n,K] @ W[K,128]; also as[n,h]=<out_h, a_src_h>, ad likewise.
// Packed f32x2 FFMA2 inner loop (2x fp32 FMA rate, full precision).
__global__ __launch_bounds__(256) void gemm_kernel(
    const float* __restrict__ X, const float* __restrict__ W,
    float* __restrict__ Out, int nrows, int K,
    const float* __restrict__ a_src, const float* __restrict__ a_dst)
{
    __shared__ float Ws[64 * 128];
    __shared__ float xs[32 * 68];
    int tid = threadIdx.x;
    int ty = tid >> 3;       // row in tile
    int tx = tid & 7;        // col group
    int row0 = blockIdx.x * 32;
    int row = row0 + ty;

    unsigned long long accu[8];   // 4 heads x 2 f32x2 pairs
#pragma unroll
    for (int i = 0; i < 8; i++) accu[i] = 0ull;

    for (int k0 = 0; k0 < K; k0 += 64) {
        const float4* Wg = (const float4*)(W + k0 * 128);
        float4* Wsv = (float4*)Ws;
        for (int i = tid; i < 64 * 128 / 4; i += 256) Wsv[i] = Wg[i];
        for (int i = tid; i < 32 * 64; i += 256) {
            int r = i >> 6, k = i & 63;
            int gr = row0 + r;
            xs[r * 68 + k] = (gr < nrows) ? X[gr * K + k0 + k] : 0.0f;
        }
        __syncthreads();
#pragma unroll 4
        for (int k = 0; k < 64; k++) {
            float xv = xs[ty * 68 + k];
            unsigned long long xp;
            asm("mov.b64 %0, {%1, %1};" : "=l"(xp) : "r"(__float_as_int(xv)));
            const float* wr = Ws + k * 128 + tx * 4;
#pragma unroll
            for (int i = 0; i < 4; i++) {
                ulonglong2 w2 = *(const ulonglong2*)(wr + i * 32);
                FFMA2(accu[2 * i],     xp, w2.x, accu[2 * i]);
                FFMA2(accu[2 * i + 1], xp, w2.y, accu[2 * i + 1]);
            }
        }
        __syncthreads();
    }

    // fused alpha: per head i, dot over 8-lane group (same ty)
    float as4[4], ad4[4];
#pragma unroll
    for (int i = 0; i < 4; i++) {
        float2 lo = *(float2*)&accu[2 * i];
        float2 hi = *(float2*)&accu[2 * i + 1];
        int col = i * 32 + tx * 4;
        float4 av = *(const float4*)(a_src + col);
        float4 dv = *(const float4*)(a_dst + col);
        float s1 = lo.x * av.x + lo.y * av.y + hi.x * av.z + hi.y * av.w;
        float s2 = lo.x * dv.x + lo.y * dv.y + hi.x * dv.z + hi.y * dv.w;
#pragma unroll
        for (int off = 4; off; off >>= 1) {
            s1 += __shfl_xor_sync(0xffffffffu, s1, off);
            s2 += __shfl_xor_sync(0xffffffffu, s2, off);
        }
        as4[i] = s1; ad4[i] = s2;
    }
    if (row < nrows) {
        if (tx == 0) {
            *(float4*)&g_as[row * 4] = make_float4(as4[0], as4[1], as4[2], as4[3]);
            *(float4*)&g_ad[row * 4] = make_float4(ad4[0], ad4[1], ad4[2], ad4[3]);
        }
        ulonglong2* o = (ulonglong2*)(Out + row * 128);
#pragma unroll
        for (int i = 0; i < 4; i++) o[i * 8 + tx] = make_ulonglong2(accu[2 * i], accu[2 * i + 1]);
    }
}

// ---------------- aggregation: one warp per dst node, two-pass softmax ----------------
__global__ __launch_bounds__(256) void agg_kernel(
    const float* __restrict__ hbuf, const float* __restrict__ bias,
    float* __restrict__ outbuf)
{
    __shared__ int    s_src[8][32];
    __shared__ float4 s_p[8][32];

    int wi = threadIdx.x >> 5;
    int n = (blockIdx.x * blockDim.x + threadIdx.x) >> 5;
    if (n >= NN) return;
    int lane = threadIdx.x & 31;
    int head = lane >> 3;
    int col = head * 32 + (lane & 7) * 4;

    float4 adv = *(const float4*)&g_ad[n * 4];
    int beg = g_rowoff[n], end = g_rowoff[n + 1];

    // pass 1: per-head max (edge-parallel)
    float4 mx = make_float4(-1e30f, -1e30f, -1e30f, -1e30f);
    for (int p = beg + lane; p < end; p += 32) {
        int s = __ldg(&g_csr[p]);
        float4 a = __ldg((const float4*)&g_as[s * 4]);
        float e;
        e = a.x + adv.x; mx.x = fmaxf(mx.x, fmaxf(e, NEG * e));
        e = a.y + adv.y; mx.y = fmaxf(mx.y, fmaxf(e, NEG * e));
        e = a.z + adv.z; mx.z = fmaxf(mx.z, fmaxf(e, NEG * e));
        e = a.w + adv.w; mx.w = fmaxf(mx.w, fmaxf(e, NEG * e));
    }
#pragma unroll
    for (int off = 16; off; off >>= 1) {
        mx.x = fmaxf(mx.x, __shfl_xor_sync(0xffffffffu, mx.x, off));
        mx.y = fmaxf(mx.y, __shfl_xor_sync(0xffffffffu, mx.y, off));
        mx.z = fmaxf(mx.z, __shfl_xor_sync(0xffffffffu, mx.z, off));
        mx.w = fmaxf(mx.w, __shfl_xor_sync(0xffffffffu, mx.w, off));
    }

    // pass 2
    float4 a0 = make_float4(0.f, 0.f, 0.f, 0.f);
    float4 a1 = a0, a2 = a0, a3 = a0;
    float4 ss = a0;

    for (int p0 = beg; p0 < end; p0 += 32) {
        int cnt = min(32, end - p0);
        float4 pv = make_float4(0.f, 0.f, 0.f, 0.f);
        int s = 0;
        if (lane < cnt) {
            s = __ldg(&g_csr[p0 + lane]);
            float4 a = __ldg((const float4*)&g_as[s * 4]);
            float e;
            e = a.x + adv.x; e = fmaxf(e, NEG * e); pv.x = __expf(e - mx.x);
            e = a.y + adv.y; e = fmaxf(e, NEG * e); pv.y = __expf(e - mx.y);
            e = a.z + adv.z; e = fmaxf(e, NEG * e); pv.z = __expf(e - mx.z);
            e = a.w + adv.w; e = fmaxf(e, NEG * e); pv.w = __expf(e - mx.w);
            ss.x += pv.x; ss.y += pv.y; ss.z += pv.z; ss.w += pv.w;
        }
        s_src[wi][lane] = s;
        s_p[wi][lane] = pv;
        __syncwarp();
        int j = 0;
        for (; j + 4 <= cnt; j += 4) {
            int s0 = s_src[wi][j + 0];
            int s1 = s_src[wi][j + 1];
            int s2 = s_src[wi][j + 2];
            int s3 = s_src[wi][j + 3];
            float p0f = ((const float*)&s_p[wi][j + 0])[head];
            float p1f = ((const float*)&s_p[wi][j + 1])[head];
            float p2f = ((const float*)&s_p[wi][j + 2])[head];
            float p3f = ((const float*)&s_p[wi][j + 3])[head];
            float4 h0 = __ldg((const float4*)(hbuf + s0 * 128 + col));
            float4 h1 = __ldg((const float4*)(hbuf + s1 * 128 + col));
            float4 h2 = __ldg((const float4*)(hbuf + s2 * 128 + col));
            float4 h3 = __ldg((const float4*)(hbuf + s3 * 128 + col));
            a0.x = fmaf(p0f, h0.x, a0.x); a0.y = fmaf(p0f, h0.y, a0.y);
            a0.z = fmaf(p0f, h0.z, a0.z); a0.w = fmaf(p0f, h0.w, a0.w);
            a1.x = fmaf(p1f, h1.x, a1.x); a1.y = fmaf(p1f, h1.y, a1.y);
            a1.z = fmaf(p1f, h1.z, a1.z); a1.w = fmaf(p1f, h1.w, a1.w);
            a2.x = fmaf(p2f, h2.x, a2.x); a2.y = fmaf(p2f, h2.y, a2.y);
            a2.z = fmaf(p2f, h2.z, a2.z); a2.w = fmaf(p2f, h2.w, a2.w);
            a3.x = fmaf(p3f, h3.x, a3.x); a3.y = fmaf(p3f, h3.y, a3.y);
            a3.z = fmaf(p3f, h3.z, a3.z); a3.w = fmaf(p3f, h3.w, a3.w);
        }
        for (; j < cnt; j++) {
            int sj = s_src[wi][j];
            float pj = ((const float*)&s_p[wi][j])[head];
            float4 hv = __ldg((const float4*)(hbuf + sj * 128 + col));
            a0.x = fmaf(pj, hv.x, a0.x); a0.y = fmaf(pj, hv.y, a0.y);
            a0.z = fmaf(pj, hv.z, a0.z); a0.w = fmaf(pj, hv.w, a0.w);
        }
        __syncwarp();
    }

    float4 acc;
    acc.x = (a0.x + a1.x) + (a2.x + a3.x);
    acc.y = (a0.y + a1.y) + (a2.y + a3.y);
    acc.z = (a0.z + a1.z) + (a2.z + a3.z);
    acc.w = (a0.w + a1.w) + (a2.w + a3.w);

#pragma unroll
    for (int off = 16; off; off >>= 1) {
        ss.x += __shfl_xor_sync(0xffffffffu, ss.x, off);
        ss.y += __shfl_xor_sync(0xffffffffu, ss.y, off);
        ss.z += __shfl_xor_sync(0xffffffffu, ss.z, off);
        ss.w += __shfl_xor_sync(0xffffffffu, ss.w, off);
    }
    float sh = (head == 0) ? ss.x : (head == 1) ? ss.y : (head == 2) ? ss.z : ss.w;
    float inv = 1.0f / (sh + 1e-16f);

    float4 b = *(const float4*)(bias + col);
    float4 o;
    o.x = acc.x * inv + b.x; o.x = fmaxf(o.x, NEG * o.x);
    o.y = acc.y * inv + b.y; o.y = fmaxf(o.y, NEG * o.y);
    o.z = acc.z * inv + b.z; o.z = fmaxf(o.z, NEG * o.z);
    o.w = acc.w * inv + b.w; o.w = fmaxf(o.w, NEG * o.w);
    *(float4*)(outbuf + n * 128 + col) = o;
}

// ---------------- pooling: segmented over sorted batch ----------------
__global__ __launch_bounds__(512) void pool_kernel(const float* __restrict__ y) {
    __shared__ float sh[3][128];
    int g = blockIdx.x;
    int s = g_goff[g], e = g_goff[g + 1];
    int c = threadIdx.x & 127;
    int r = threadIdx.x >> 7;   // 0..3
    float acc = 0.f;
    for (int i = s + r; i < e; i += 4) acc += y[i * 128 + c];
    if (r) sh[r - 1][c] = acc;
    __syncthreads();
    if (!r) g_pool[g * 128 + c] = ((acc + sh[0][c]) + (sh[1][c] + sh[2][c]));
}

// ---------------- head ----------------
__global__ void head_kernel(const float* __restrict__ fc_w, const float* __restrict__ fc_b,
                            const float* __restrict__ bn_g, const float* __restrict__ bn_b,
                            float* __restrict__ out)
{
    int g = blockIdx.x;
    int l = threadIdx.x;
    const float* pr = g_pool + g * HID;
    float s = 0.f;
#pragma unroll 8
    for (int k = 0; k < HID; k++) s = fmaf(pr[k], fc_w[k * LAT + l], s);
    s += fc_b[l];
    const float inv = 0.999995000037499688f;  // 1/sqrt(1 + 1e-5)
    out[g * LAT + l] = bn_g[l] * s * inv + bn_b[l];
}

// ---------------- launch ----------------
extern "C" void kernel_launch(void* const* d_in, const int* in_sizes, int n_in,
                              void* d_out, int out_size)
{
    const float* x       = (const float*)d_in[0];
    const int*   eidx    = (const int*)  d_in[1];
    const int*   batch   = (const int*)  d_in[2];
    const float* W0      = (const float*)d_in[3];
    const float* a_src0  = (const float*)d_in[4];
    const float* a_dst0  = (const float*)d_in[5];
    const float* b0      = (const float*)d_in[6];
    const float* W1      = (const float*)d_in[7];
    const float* a_src1  = (const float*)d_in[8];
    const float* a_dst1  = (const float*)d_in[9];
    const float* b1      = (const float*)d_in[10];
    const float* W2      = (const float*)d_in[11];
    const float* a_src2  = (const float*)d_in[12];
    const float* a_dst2  = (const float*)d_in[13];
    const float* b2      = (const float*)d_in[14];
    const float* fc_w    = (const float*)d_in[15];
    const float* fc_b    = (const float*)d_in[16];
    const float* bn_g    = (const float*)d_in[17];
    const float* bn_b    = (const float*)d_in[18];
    float* out = (float*)d_out;

    const int* src = eidx;
    const int* dst = eidx + EE;

    float *ph, *py;
    cudaGetSymbolAddress((void**)&ph, g_h);
    cudaGetSymbolAddress((void**)&py, g_y);

    init_kernel<<<(NN + 255) / 256, 256>>>();
    hist_kernel<<<(EE + 255) / 256, 256>>>(dst);
    scan_kernel<<<1, 1024>>>();
    scatter_kernel<<<(EE + NN + 255) / 256, 256>>>(src, dst);
    gbound_kernel<<<(NN + 255) / 256, 256>>>(batch);

    const int gemm_grid = (NN + 31) / 32;
    const int warp_grid = (NN + 7) / 8;

    gemm_kernel<<<gemm_grid, 256>>>(x, W0, ph, NN, 64, a_src0, a_dst0);
    agg_kernel<<<warp_grid, 256>>>(ph, b0, py);

    gemm_kernel<<<gemm_grid, 256>>>(py, W1, ph, NN, 128, a_src1, a_dst1);
    agg_kernel<<<warp_grid, 256>>>(ph, b1, py);

    gemm_kernel<<<gemm_grid, 256>>>(py, W2, ph, NN, 128, a_src2, a_dst2);
    agg_kernel<<<warp_grid, 256>>>(ph, b2, py);

    pool_kernel<<<GG, 512>>>(py);
    head_kernel<<<GG, LAT>>>(fc_w, fc_b, bn_g, bn_b, out);
}